// round 8
// baseline (speedup 1.0000x reference)
#include <cuda_runtime.h>
#include <cstdint>

#define NODES 20000
#define BATCH 32
#define FEAT  64
#define EIG   16
#define NOUT  64

#define CHUNK1 500
#define NCHUNK 40        // 20000 = 40 * 500 exactly

#define TN3    512
#define NBLK3  40        // 40*512 = 20480 >= 20000 (guarded)

#define RSTRIDE 20       // red-buffer row stride in floats: 80 B = 16B-aligned
                         // (17 in R5 broke ulonglong2/float4 alignment -> trap)

typedef unsigned long long ull;

// Scratch (static device globals: allocation-free per harness rules)
__device__ float g_zpart[(size_t)NCHUNK * BATCH * FEAT * EIG]; // 5.24 MB
__device__ float g_z[BATCH * FEAT * EIG];                      // 128 KB
__device__ float g_w[BATCH * NOUT * EIG];                      // 128 KB

// ---- packed fp32x2 helpers (full-rate fp32 on sm_103a goes through FFMA2) ----
__device__ __forceinline__ ull pack2(float lo, float hi) {
    ull r; asm("mov.b64 %0, {%1, %2};" : "=l"(r) : "f"(lo), "f"(hi)); return r;
}
__device__ __forceinline__ float2 unpack2(ull v) {
    float2 r; asm("mov.b64 {%0, %1}, %2;" : "=f"(r.x), "=f"(r.y) : "l"(v)); return r;
}
__device__ __forceinline__ ull ffma2(ull a, ull b, ull c) {
    ull d; asm("fma.rn.f32x2 %0, %1, %2, %3;" : "=l"(d) : "l"(a), "l"(b), "l"(c)); return d;
}
__device__ __forceinline__ ull fmul2(ull a, ull b) {
    ull d; asm("mul.rn.f32x2 %0, %1, %2;" : "=l"(d) : "l"(a), "l"(b)); return d;
}
__device__ __forceinline__ ull fadd2(ull a, ull b) {
    ull d; asm("add.rn.f32x2 %0, %1, %2;" : "=l"(d) : "l"(a), "l"(b)); return d;
}

// ============================================================================
// Stage 1: z[b,i,f] = sum_m V[m,f] * x[b,m,i]
// Block = (chunk c of 500 nodes, batch b), 256 threads = 8 warps.
// Warp = stripe s = tid>>5 : handles nodes m = s, s+8, ...
// Lane l owns i = {2l, 2l+1} x ALL 16 f  (16 FFMA2 accumulators).
// x: LDG.64 coalesced (warp = full 256B row, read once -> DRAM-optimal).
// V: lane-invariant LDG.128 -> L1tex DEDUPS (1 wavefront), unlike the smem
//    crossbar which replicates broadcast to 512B (the R3/R4 ~70us k1 bug).
// Epilogue: 8-stripe reduction via 16B-aligned padded smem (stride 20 floats).
// ============================================================================
__global__ __launch_bounds__(256)
void k1_project(const float* __restrict__ x, const float* __restrict__ V) {
    __shared__ __align__(16) float red[8 * 64 * RSTRIDE];   // 40 KB
    const int b = blockIdx.y, c = blockIdx.x;
    const int m0 = c * CHUNK1;
    const int tid = threadIdx.x;
    const int s = tid >> 5, l = tid & 31;

    const float* xb = x + ((size_t)b * NODES + m0) * FEAT + 2 * l;
    const float* Vb = V + (size_t)m0 * EIG;

    ull aA0=0,aA1=0,aA2=0,aA3=0,aA4=0,aA5=0,aA6=0,aA7=0;
    ull aB0=0,aB1=0,aB2=0,aB3=0,aB4=0,aB5=0,aB6=0,aB7=0;

    #pragma unroll 2
    for (int mi = s; mi < CHUNK1; mi += 8) {
        float2 xv = *(const float2*)(xb + (size_t)mi * FEAT);      // coalesced
        const ulonglong2* vp = (const ulonglong2*)(Vb + mi * EIG); // lane-invariant
        ulonglong2 q0 = vp[0], q1 = vp[1], q2 = vp[2], q3 = vp[3];
        ull xx0 = pack2(xv.x, xv.x);
        ull xx1 = pack2(xv.y, xv.y);
        aA0 = ffma2(xx0, q0.x, aA0);  aB0 = ffma2(xx1, q0.x, aB0);
        aA1 = ffma2(xx0, q0.y, aA1);  aB1 = ffma2(xx1, q0.y, aB1);
        aA2 = ffma2(xx0, q1.x, aA2);  aB2 = ffma2(xx1, q1.x, aB2);
        aA3 = ffma2(xx0, q1.y, aA3);  aB3 = ffma2(xx1, q1.y, aB3);
        aA4 = ffma2(xx0, q2.x, aA4);  aB4 = ffma2(xx1, q2.x, aB4);
        aA5 = ffma2(xx0, q2.y, aA5);  aB5 = ffma2(xx1, q2.y, aB5);
        aA6 = ffma2(xx0, q3.x, aA6);  aB6 = ffma2(xx1, q3.x, aB6);
        aA7 = ffma2(xx0, q3.y, aA7);  aB7 = ffma2(xx1, q3.y, aB7);
    }

    // per-stripe partials: red[s][i][f], row stride 20 floats (80B, 16B-aligned)
    {
        float* pA = red + (s * 64 + 2 * l) * RSTRIDE;
        float* pB = pA + RSTRIDE;
        ulonglong2 t;
        t.x = aA0; t.y = aA1; *(ulonglong2*)(pA + 0)  = t;
        t.x = aA2; t.y = aA3; *(ulonglong2*)(pA + 4)  = t;
        t.x = aA4; t.y = aA5; *(ulonglong2*)(pA + 8)  = t;
        t.x = aA6; t.y = aA7; *(ulonglong2*)(pA + 12) = t;
        t.x = aB0; t.y = aB1; *(ulonglong2*)(pB + 0)  = t;
        t.x = aB2; t.y = aB3; *(ulonglong2*)(pB + 4)  = t;
        t.x = aB4; t.y = aB5; *(ulonglong2*)(pB + 8)  = t;
        t.x = aB6; t.y = aB7; *(ulonglong2*)(pB + 12) = t;
    }
    __syncthreads();

    // reduce 8 stripes (fixed order -> deterministic), write partial z
    {
        const int ii = tid >> 2, fq = tid & 3;    // 64 i x 4 f-quads
        float4 acc = make_float4(0.f, 0.f, 0.f, 0.f);
        #pragma unroll
        for (int ss = 0; ss < 8; ss++) {
            float4 v = *(const float4*)(red + (ss * 64 + ii) * RSTRIDE + fq * 4);
            acc.x += v.x; acc.y += v.y; acc.z += v.z; acc.w += v.w;
        }
        *(float4*)(g_zpart + ((size_t)c * BATCH + b) * (FEAT * EIG)
                   + ii * EIG + fq * 4) = acc;
    }
}

// ============================================================================
// Stage 1b: reduce partial z over chunks (fixed order -> deterministic)
// ============================================================================
__global__ __launch_bounds__(256)
void k1_reduce() {
    const int q = blockIdx.x * 256 + threadIdx.x;   // over 8192 float4
    const float4* zp = (const float4*)g_zpart;
    float4 s = make_float4(0.f, 0.f, 0.f, 0.f);
    #pragma unroll
    for (int c = 0; c < NCHUNK; c++) {
        float4 v = zp[(size_t)c * (BATCH * FEAT * EIG / 4) + q];
        s.x += v.x; s.y += v.y; s.z += v.z; s.w += v.w;
    }
    ((float4*)g_z)[q] = s;
}

// ============================================================================
// Stage 2: w[b,j,e] = sum_{i,f} G[j,i,e,f] * z[b,i,f]
// smem-free: z read directly from g_z (L1/L2-resident; LDG dedups the
// low-unique-address lane pattern, no crossbar replication).
// ============================================================================
__global__ __launch_bounds__(128)
void k2_mix(const float* __restrict__ G) {
    const int bg = blockIdx.x;     // 0..3
    const int j  = blockIdx.y;     // 0..63
    const int tid = threadIdx.x;   // 128
    const int bl = tid >> 4;       // 0..7
    const int e  = tid & 15;
    const float* Gje  = G + (size_t)j * (FEAT * EIG * EIG) + e * EIG;
    const float* zrow = g_z + ((size_t)bg * 8 + bl) * (FEAT * EIG);
    ull acc0 = 0ULL, acc1 = 0ULL, acc2 = 0ULL, acc3 = 0ULL;
    #pragma unroll 8
    for (int i = 0; i < FEAT; i++) {
        const ulonglong2* gp = (const ulonglong2*)(Gje + (size_t)i * (EIG * EIG));
        const ulonglong2* zq = (const ulonglong2*)(zrow + i * EIG);
        ulonglong2 g0 = gp[0], g1 = gp[1], g2 = gp[2], g3 = gp[3];
        ulonglong2 z0 = zq[0], z1 = zq[1], z2 = zq[2], z3 = zq[3];
        acc0 = ffma2(g0.x, z0.x, acc0);
        acc1 = ffma2(g0.y, z0.y, acc1);
        acc2 = ffma2(g1.x, z1.x, acc2);
        acc3 = ffma2(g1.y, z1.y, acc3);
        acc0 = ffma2(g2.x, z2.x, acc0);
        acc1 = ffma2(g2.y, z2.y, acc1);
        acc2 = ffma2(g3.x, z3.x, acc2);
        acc3 = ffma2(g3.y, z3.y, acc3);
    }
    ull s = fadd2(fadd2(acc0, acc1), fadd2(acc2, acc3));
    float2 f = unpack2(s);
    g_w[((size_t)bg * 8 + bl) * (NOUT * EIG) + j * EIG + e] = f.x + f.y;
}

// ============================================================================
// Stage 3: out[b,n,j] = sum_e V[n,e] * w[b,j,e]
// Block = (512-node tile, batch); warp wq owns 64 consecutive nodes.
// w packed into registers once per block (via padded wsT smem transpose);
// V read per node via lane-invariant LDG.128 (L1tex dedup -> 1 wavefront,
// vs 4 crossbar cycles for the R4 smem broadcast). fma-pipe/DRAM-write bound.
// ============================================================================
__global__ __launch_bounds__(256)
void k3_expand(const float* __restrict__ V, float* __restrict__ out) {
    __shared__ __align__(16) float wsT[EIG * 65];      // 4.2 KB padded transpose
    const int b  = blockIdx.y;
    const int n0 = blockIdx.x * TN3;
    const int tid = threadIdx.x;

    // load w[b] transposed: wsT[e*65 + j] = w[b][j][e]
    {
        float4 fw = ((const float4*)(g_w + (size_t)b * NOUT * EIG))[tid];
        int j = tid >> 2, e0 = (tid & 3) * 4;
        wsT[(e0 + 0) * 65 + j] = fw.x;
        wsT[(e0 + 1) * 65 + j] = fw.y;
        wsT[(e0 + 2) * 65 + j] = fw.z;
        wsT[(e0 + 3) * 65 + j] = fw.w;
    }
    __syncthreads();

    const int jp = tid & 31;     // j pair: j = 2*jp, 2*jp+1
    const int wq = tid >> 5;     // warp -> 64-node slice
    ull w0[8], w1[8];
    #pragma unroll
    for (int k = 0; k < 8; k++) {
        w0[k] = pack2(wsT[(2 * k) * 65 + 2 * jp],     wsT[(2 * k + 1) * 65 + 2 * jp]);
        w1[k] = pack2(wsT[(2 * k) * 65 + 2 * jp + 1], wsT[(2 * k + 1) * 65 + 2 * jp + 1]);
    }

    const int nw = n0 + wq * 64;
    const int trip = (nw + 64 <= NODES) ? 64 : (nw < NODES ? NODES - nw : 0);
    float* ob = out + (size_t)b * NODES * NOUT;
    #pragma unroll 4
    for (int p = 0; p < trip; p++) {
        const int n = nw + p;
        const ulonglong2* vp = (const ulonglong2*)(V + (size_t)n * EIG); // dedup LDG
        ulonglong2 va = vp[0], vb = vp[1], vc = vp[2], vd = vp[3];
        ull a0 = fmul2(va.x, w0[0]);
        ull a1 = fmul2(va.y, w0[1]);
        a0 = ffma2(vb.x, w0[2], a0);
        a1 = ffma2(vb.y, w0[3], a1);
        a0 = ffma2(vc.x, w0[4], a0);
        a1 = ffma2(vc.y, w0[5], a1);
        a0 = ffma2(vd.x, w0[6], a0);
        a1 = ffma2(vd.y, w0[7], a1);
        float2 f0 = unpack2(fadd2(a0, a1));
        ull c0 = fmul2(va.x, w1[0]);
        ull c1 = fmul2(va.y, w1[1]);
        c0 = ffma2(vb.x, w1[2], c0);
        c1 = ffma2(vb.y, w1[3], c1);
        c0 = ffma2(vc.x, w1[4], c0);
        c1 = ffma2(vc.y, w1[5], c1);
        c0 = ffma2(vd.x, w1[6], c0);
        c1 = ffma2(vd.y, w1[7], c1);
        float2 f1 = unpack2(fadd2(c0, c1));
        *(float2*)(ob + (size_t)n * NOUT + 2 * jp) =
            make_float2(f0.x + f0.y, f1.x + f1.y);
    }
}

extern "C" void kernel_launch(void* const* d_in, const int* in_sizes, int n_in,
                              void* d_out, int out_size) {
    const float* x = (const float*)d_in[0];   // (32, 20000, 64) fp32
    const float* V = (const float*)d_in[1];   // (20000, 16)     fp32
    const float* G = (const float*)d_in[2];   // (64, 64, 16, 16) fp32
    float* out = (float*)d_out;               // (32, 20000, 64) fp32

    k1_project<<<dim3(NCHUNK, BATCH), 256>>>(x, V);
    k1_reduce<<<32, 256>>>();
    k2_mix<<<dim3(4, NOUT), 128>>>(G);
    k3_expand<<<dim3(NBLK3, BATCH), 256>>>(V, out);
}

// round 9
// speedup vs baseline: 1.0935x; 1.0935x over previous
#include <cuda_runtime.h>
#include <cstdint>

#define NODES 20000
#define BATCH 32
#define FEAT  64
#define EIG   16
#define NOUT  64

#define CH1    512
#define NCHUNK 40        // 40*512 = 20480 >= 20000; last block has exactly 32 nodes

#define TN3    512
#define NBLK3  40        // 40*512 = 20480; last block ng=0 covers 19968..19999 exactly

typedef unsigned long long ull;

// Scratch (static device globals: allocation-free per harness rules)
__device__ float g_zpart[(size_t)NCHUNK * BATCH * FEAT * EIG]; // 5.24 MB
__device__ float g_z[BATCH * FEAT * EIG];                      // 128 KB
__device__ float g_w[BATCH * NOUT * EIG];                      // 128 KB

// ---- packed fp32x2 helpers (full-rate fp32 on sm_103a goes through FFMA2) ----
__device__ __forceinline__ ull pack2(float lo, float hi) {
    ull r; asm("mov.b64 %0, {%1, %2};" : "=l"(r) : "f"(lo), "f"(hi)); return r;
}
__device__ __forceinline__ float2 unpack2(ull v) {
    float2 r; asm("mov.b64 {%0, %1}, %2;" : "=f"(r.x), "=f"(r.y) : "l"(v)); return r;
}
__device__ __forceinline__ ull ffma2(ull a, ull b, ull c) {
    ull d; asm("fma.rn.f32x2 %0, %1, %2, %3;" : "=l"(d) : "l"(a), "l"(b), "l"(c)); return d;
}
__device__ __forceinline__ ull fadd2(ull a, ull b) {
    ull d; asm("add.rn.f32x2 %0, %1, %2;" : "=l"(d) : "l"(a), "l"(b)); return d;
}

// ============================================================================
// Stage 1: z[b,i,f] = sum_m V[m,f] * x[b,m,i]
// Block = (512-node chunk, batch), 256 threads.
// Thread (st, fg, ig): st = tid>>4 (16 node-stripes), fg = (tid>>3)&1 (f-oct),
// ig = tid&7 (i-oct). Thread owns an 8i x 8f z-tile (32 ull accum) -> per node
// only x 32B (gmem) + V 32B (smem) feed 64 FMA = 0.5 B/FMA on EACH path,
// the crossbar/fma balance point (the R3-R8 kernels were 3x over on V).
// Reduction: shfl_xor(16) pairs stripes (16->8), one padded-smem wave (rows of
// 18 floats; ull stores 8B-aligned), final 256-thread sweep -> g_zpart.
// ============================================================================
__global__ __launch_bounds__(256)
void k1_project(const float* __restrict__ x, const float* __restrict__ V) {
    __shared__ __align__(16) float sm[9216];   // 36 KB: V panel (<=8192 fl), then red buf
    const int b = blockIdx.y, c = blockIdx.x;
    const int m0 = c * CH1;
    const int Nloc = (NODES - m0 < CH1) ? (NODES - m0) : CH1;   // 512 or 32
    const int tid = threadIdx.x;
    const int st = tid >> 4, fg = (tid >> 3) & 1, ig = tid & 7;

    // cooperative load: V panel [Nloc][16] (Nloc*4 float4 slots)
    {
        const float4* src = (const float4*)(V + (size_t)m0 * EIG);
        float4* dst = (float4*)sm;
        for (int idx = tid; idx < Nloc * 4; idx += 256) dst[idx] = src[idx];
    }
    __syncthreads();

    const float* xb = x + ((size_t)b * NODES + m0) * FEAT + ig * 8;

    ull a[8][4];
    #pragma unroll
    for (int ii = 0; ii < 8; ii++)
        #pragma unroll
        for (int fq = 0; fq < 4; fq++) a[ii][fq] = 0ULL;

    const int trip = Nloc >> 4;    // 32 or 2 (uniform across threads)
    #pragma unroll 2
    for (int k = 0; k < trip; k++) {
        const int m = st + (k << 4);
        float4 x0 = *(const float4*)(xb + (size_t)m * FEAT);
        float4 x1 = *(const float4*)(xb + (size_t)m * FEAT + 4);
        ulonglong2 v0 = *(const ulonglong2*)(sm + m * EIG + fg * 8);
        ulonglong2 v1 = *(const ulonglong2*)(sm + m * EIG + fg * 8 + 4);
        float xs_[8] = {x0.x, x0.y, x0.z, x0.w, x1.x, x1.y, x1.z, x1.w};
        #pragma unroll
        for (int ii = 0; ii < 8; ii++) {
            ull xx = pack2(xs_[ii], xs_[ii]);
            a[ii][0] = ffma2(xx, v0.x, a[ii][0]);
            a[ii][1] = ffma2(xx, v0.y, a[ii][1]);
            a[ii][2] = ffma2(xx, v1.x, a[ii][2]);
            a[ii][3] = ffma2(xx, v1.y, a[ii][3]);
        }
    }

    // pair-reduce stripes st <-> st^1 via shuffle (lane partner = lane ^ 16)
    #pragma unroll
    for (int ii = 0; ii < 8; ii++)
        #pragma unroll
        for (int fq = 0; fq < 4; fq++) {
            ull o = __shfl_xor_sync(0xffffffffu, a[ii][fq], 16);
            a[ii][fq] = fadd2(a[ii][fq], o);
        }

    __syncthreads();   // V panel dead; reuse sm as reduction buffer

    // 8 stripe-buffers, rows of 18 floats (8B-aligned ull slots, conflict-mild)
    if ((st & 1) == 0) {
        const int sb = st >> 1;
        #pragma unroll
        for (int ii = 0; ii < 8; ii++) {
            float* p = sm + (size_t)(sb * 64 + ig * 8 + ii) * 18 + fg * 8;
            #pragma unroll
            for (int fq = 0; fq < 4; fq++)
                *(ull*)(p + fq * 2) = a[ii][fq];
        }
    }
    __syncthreads();

    // final: thread -> one (i, f-quad): sum 8 buffers, write partial z
    {
        const int i = tid >> 2, qd = tid & 3;
        float s0 = 0.f, s1 = 0.f, s2 = 0.f, s3 = 0.f;
        #pragma unroll
        for (int sb = 0; sb < 8; sb++) {
            const float* p = sm + (size_t)(sb * 64 + i) * 18 + qd * 4;
            float2 f0 = unpack2(*(const ull*)(p));
            float2 f1 = unpack2(*(const ull*)(p + 2));
            s0 += f0.x; s1 += f0.y; s2 += f1.x; s3 += f1.y;
        }
        *(float4*)(g_zpart + ((size_t)c * BATCH + b) * (FEAT * EIG)
                   + i * EIG + qd * 4) = make_float4(s0, s1, s2, s3);
    }
}

// ============================================================================
// Stage 1b: reduce partial z over chunks (fixed order -> deterministic)
// ============================================================================
__global__ __launch_bounds__(256)
void k1_reduce() {
    const int q = blockIdx.x * 256 + threadIdx.x;   // over 8192 float4
    const float4* zp = (const float4*)g_zpart;
    float4 s = make_float4(0.f, 0.f, 0.f, 0.f);
    #pragma unroll
    for (int c = 0; c < NCHUNK; c++) {
        float4 v = zp[(size_t)c * (BATCH * FEAT * EIG / 4) + q];
        s.x += v.x; s.y += v.y; s.z += v.z; s.w += v.w;
    }
    ((float4*)g_z)[q] = s;
}

// ============================================================================
// Stage 2: w[b,j,e] = sum_{i,f} G[j,i,e,f] * z[b,i,f]
// ============================================================================
__global__ __launch_bounds__(128)
void k2_mix(const float* __restrict__ G) {
    const int bg = blockIdx.x;     // 0..3
    const int j  = blockIdx.y;     // 0..63
    const int tid = threadIdx.x;   // 128
    const int bl = tid >> 4;       // 0..7
    const int e  = tid & 15;
    const float* Gje  = G + (size_t)j * (FEAT * EIG * EIG) + e * EIG;
    const float* zrow = g_z + ((size_t)bg * 8 + bl) * (FEAT * EIG);
    ull acc0 = 0ULL, acc1 = 0ULL, acc2 = 0ULL, acc3 = 0ULL;
    #pragma unroll 8
    for (int i = 0; i < FEAT; i++) {
        const ulonglong2* gp = (const ulonglong2*)(Gje + (size_t)i * (EIG * EIG));
        const ulonglong2* zq = (const ulonglong2*)(zrow + i * EIG);
        ulonglong2 g0 = gp[0], g1 = gp[1], g2 = gp[2], g3 = gp[3];
        ulonglong2 z0 = zq[0], z1 = zq[1], z2 = zq[2], z3 = zq[3];
        acc0 = ffma2(g0.x, z0.x, acc0);
        acc1 = ffma2(g0.y, z0.y, acc1);
        acc2 = ffma2(g1.x, z1.x, acc2);
        acc3 = ffma2(g1.y, z1.y, acc3);
        acc0 = ffma2(g2.x, z2.x, acc0);
        acc1 = ffma2(g2.y, z2.y, acc1);
        acc2 = ffma2(g3.x, z3.x, acc2);
        acc3 = ffma2(g3.y, z3.y, acc3);
    }
    ull s = fadd2(fadd2(acc0, acc1), fadd2(acc2, acc3));
    float2 f = unpack2(s);
    g_w[((size_t)bg * 8 + bl) * (NOUT * EIG) + j * EIG + e] = f.x + f.y;
}

// ============================================================================
// Stage 3: out[b,n,j] = sum_e V[n,e] * w[b,j,e]
// Block = (512-node tile, batch), 256 threads. Thread (jq, ng): jq = tid&15
// (j-quad), ng = tid>>4 (32-node slice). w[4j][16e] lives in REGISTERS as
// e-major j-pair packs for the entire node stream (loaded once) -> per node
// only V 64B is fetched (smem, lane-distinct-ish) for 64 FMA. No broadcast
// amplification; stores float4-coalesced (warp = 2 nodes x 16 jq).
// ============================================================================
__global__ __launch_bounds__(256)
void k3_expand(const float* __restrict__ V, float* __restrict__ out) {
    __shared__ __align__(16) float vs[TN3 * EIG];   // 32 KB
    const int b   = blockIdx.y;
    const int nb0 = blockIdx.x * TN3;
    const int Nloc = (NODES - nb0 < TN3) ? (NODES - nb0) : TN3;   // 512 or 32
    const int tid = threadIdx.x;
    const int jq = tid & 15, ng = tid >> 4;

    // cooperative load: V tile [Nloc][16]
    {
        const float4* src = (const float4*)(V + (size_t)nb0 * EIG);
        float4* dst = (float4*)vs;
        for (int idx = tid; idx < Nloc * 4; idx += 256) dst[idx] = src[idx];
    }

    // one-time: w[b][jq*4 .. +3][:] -> e-major j-pair packs (32 ull registers)
    ull wjp[16][2];
    {
        const float* wb = g_w + (size_t)b * (NOUT * EIG) + (size_t)jq * 4 * EIG;
        float r0[16], r1[16];
        #pragma unroll
        for (int q = 0; q < 4; q++) {
            float4 u = ((const float4*)wb)[q];
            r0[q * 4 + 0] = u.x; r0[q * 4 + 1] = u.y; r0[q * 4 + 2] = u.z; r0[q * 4 + 3] = u.w;
            float4 v = ((const float4*)(wb + EIG))[q];
            r1[q * 4 + 0] = v.x; r1[q * 4 + 1] = v.y; r1[q * 4 + 2] = v.z; r1[q * 4 + 3] = v.w;
        }
        #pragma unroll
        for (int e = 0; e < 16; e++) wjp[e][0] = pack2(r0[e], r1[e]);
        #pragma unroll
        for (int q = 0; q < 4; q++) {
            float4 u = ((const float4*)(wb + 2 * EIG))[q];
            r0[q * 4 + 0] = u.x; r0[q * 4 + 1] = u.y; r0[q * 4 + 2] = u.z; r0[q * 4 + 3] = u.w;
            float4 v = ((const float4*)(wb + 3 * EIG))[q];
            r1[q * 4 + 0] = v.x; r1[q * 4 + 1] = v.y; r1[q * 4 + 2] = v.z; r1[q * 4 + 3] = v.w;
        }
        #pragma unroll
        for (int e = 0; e < 16; e++) wjp[e][1] = pack2(r0[e], r1[e]);
    }
    __syncthreads();

    const int base = ng * 32;          // this thread's node slice within the tile
    if (base < Nloc) {                 // slice is fully valid (Nloc multiple of 32)
        float* ob = out + ((size_t)b * NODES + nb0) * NOUT + jq * 4;
        #pragma unroll 2
        for (int cচ = 0; cচ < 16; cচ++) {
            const int n = base + 2 * cচ;
            const float4* va = (const float4*)(vs + n * EIG);
            float4 A0 = va[0], A1 = va[1], A2 = va[2], A3 = va[3];
            const float4* vb2 = (const float4*)(vs + (n + 1) * EIG);
            float4 B0 = vb2[0], B1 = vb2[1], B2 = vb2[2], B3 = vb2[3];
            float Ae[16] = {A0.x, A0.y, A0.z, A0.w, A1.x, A1.y, A1.z, A1.w,
                            A2.x, A2.y, A2.z, A2.w, A3.x, A3.y, A3.z, A3.w};
            float Be[16] = {B0.x, B0.y, B0.z, B0.w, B1.x, B1.y, B1.z, B1.w,
                            B2.x, B2.y, B2.z, B2.w, B3.x, B3.y, B3.z, B3.w};
            ull a00 = 0, a01 = 0, a10 = 0, a11 = 0;
            #pragma unroll
            for (int e = 0; e < 16; e++) {
                ull xx = pack2(Ae[e], Ae[e]);
                a00 = ffma2(xx, wjp[e][0], a00);
                a01 = ffma2(xx, wjp[e][1], a01);
                ull yy = pack2(Be[e], Be[e]);
                a10 = ffma2(yy, wjp[e][0], a10);
                a11 = ffma2(yy, wjp[e][1], a11);
            }
            float2 p0 = unpack2(a00), p1 = unpack2(a01);
            *(float4*)(ob + (size_t)n * NOUT) = make_float4(p0.x, p0.y, p1.x, p1.y);
            float2 q0 = unpack2(a10), q1 = unpack2(a11);
            *(float4*)(ob + (size_t)(n + 1) * NOUT) = make_float4(q0.x, q0.y, q1.x, q1.y);
        }
    }
}

extern "C" void kernel_launch(void* const* d_in, const int* in_sizes, int n_in,
                              void* d_out, int out_size) {
    const float* x = (const float*)d_in[0];   // (32, 20000, 64) fp32
    const float* V = (const float*)d_in[1];   // (20000, 16)     fp32
    const float* G = (const float*)d_in[2];   // (64, 64, 16, 16) fp32
    float* out = (float*)d_out;               // (32, 20000, 64) fp32

    k1_project<<<dim3(NCHUNK, BATCH), 256>>>(x, V);
    k1_reduce<<<32, 256>>>();
    k2_mix<<<dim3(4, NOUT), 128>>>(G);
    k3_expand<<<dim3(NBLK3, BATCH), 256>>>(V, out);
}

// round 11
// speedup vs baseline: 1.2018x; 1.0991x over previous
#include <cuda_runtime.h>
#include <cstdint>

#define NODES 20000
#define BATCH 32
#define FEAT  64
#define EIG   16
#define NOUT  64

// k1: 25 chunks x 800 nodes; 10 panels of 80 per chunk (exact: 25*800 = 20000)
#define NCHUNK 25
#define CH1    800
#define PPC    10

// k1 reduction buffer geometry: per-warp block stride 1312 = 64*20 + 32 pad
// (row extent = rskew(i)+16 <= 44 at i=63; next block starts +32 past row 63's
//  20-slot -> no overlap. R10 used (w*64+i)*20 and overlapped at boundaries.)
#define RBLK 1312

// k3: 157 tiles x 128 nodes (last tile 32), 16 batch-pairs
#define TN3    128
#define NBLK3  157

typedef unsigned long long ull;

// Scratch (static device globals: allocation-free per harness rules)
__device__ float g_zpart[(size_t)NCHUNK * BATCH * FEAT * EIG]; // 3.28 MB
__device__ float g_z[BATCH * FEAT * EIG];                      // 128 KB
__device__ float g_w[BATCH * NOUT * EIG];                      // 128 KB

// ---- packed fp32x2 helpers (full-rate fp32 on sm_103a goes through FFMA2) ----
__device__ __forceinline__ ull pack2(float lo, float hi) {
    ull r; asm("mov.b64 %0, {%1, %2};" : "=l"(r) : "f"(lo), "f"(hi)); return r;
}
__device__ __forceinline__ float2 unpack2(ull v) {
    float2 r; asm("mov.b64 {%0, %1}, %2;" : "=f"(r.x), "=f"(r.y) : "l"(v)); return r;
}
__device__ __forceinline__ ull ffma2(ull a, ull b, ull c) {
    ull d; asm("fma.rn.f32x2 %0, %1, %2, %3;" : "=l"(d) : "l"(a), "l"(b), "l"(c)); return d;
}

// skew for the k1 reduction buffer: staggers the 8 ig-groups across banks
__device__ __forceinline__ int rskew(int i) { return ((i >> 3) & 7) * 4; }

// ============================================================================
// Stage 1: z[b,i,f] = sum_m V[m,f] * x[b,m,i]
// Block = (800-node chunk, batch), 256 thr. 10 panels of 80 nodes, REGISTER-
// PREFETCH pipelined: while computing panel p from smem, panel p+1 streams
// from gmem into registers (bulk float4 loads = high MLP; R8/R9's direct-LDG
// inner loops lacked this and were DRAM-latency-bound).
// Compute: warp w takes node m = k*8+w; thread (fq = lane>>3, ig = lane&7)
// owns 8i x 4f (16 ull accum). Per warp per node: 3 LDS.128 (12 crossbar cyc)
// vs 16 FFMA2 (8 fma SM-cyc) -> near-balanced, latency-tolerant (smem lat 29).
// Epilogue: 8-warp smem reduction, per-warp padded blocks (RBLK) + skew.
// ============================================================================
__global__ __launch_bounds__(256)
void k1_project(const float* __restrict__ x, const float* __restrict__ V) {
    __shared__ __align__(16) float sm[8 * RBLK];   // 41 KB; xs/vsp alias, later red buf
    float* xs  = sm;            // panel x: 80 nodes x 64 feat = 5120 floats
    float* vsp = sm + 5120;     // panel V: 80 nodes x 16 eig  = 1280 floats
    const int b = blockIdx.y, c = blockIdx.x;
    const int m0 = c * CH1;
    const int tid = threadIdx.x;
    const int w = tid >> 5, lane = tid & 31;
    const int fq = lane >> 3, ig = lane & 7;

    const float4* xsrc = (const float4*)(x + ((size_t)b * NODES + m0) * FEAT);
    const float4* vsrc = (const float4*)(V + (size_t)m0 * EIG);

    float4 px[5];
    float4 pv0 = make_float4(0.f,0.f,0.f,0.f), pv1 = make_float4(0.f,0.f,0.f,0.f);

    // prologue: fetch panel 0 (1280 x-float4, 320 V-float4) and store to smem
    #pragma unroll
    for (int r = 0; r < 5; r++) px[r] = xsrc[tid + r * 256];
    pv0 = vsrc[tid];                       // slots 0..255
    if (tid < 64)  pv1 = vsrc[tid + 256];  // slots 256..319
    #pragma unroll
    for (int r = 0; r < 5; r++) ((float4*)xs)[tid + r * 256] = px[r];
    ((float4*)vsp)[tid] = pv0;
    if (tid < 64)  ((float4*)vsp)[tid + 256] = pv1;

    ull a[8][2];
    #pragma unroll
    for (int ii = 0; ii < 8; ii++) { a[ii][0] = 0ULL; a[ii][1] = 0ULL; }

    for (int p = 0; p < PPC; p++) {
        __syncthreads();                       // panel p visible in smem
        if (p + 1 < PPC) {                     // prefetch p+1 (hidden under compute)
            const float4* xn = xsrc + (size_t)(p + 1) * 1280;
            #pragma unroll
            for (int r = 0; r < 5; r++) px[r] = xn[tid + r * 256];
            const float4* vn = vsrc + (size_t)(p + 1) * 320;
            pv0 = vn[tid];
            if (tid < 64)  pv1 = vn[tid + 256];
        }
        #pragma unroll
        for (int k = 0; k < 10; k++) {
            const int m = k * 8 + w;
            float4 x0 = *(const float4*)(xs + m * 64 + ig * 8);
            float4 x1 = *(const float4*)(xs + m * 64 + ig * 8 + 4);
            ulonglong2 vv = *(const ulonglong2*)(vsp + m * 16 + fq * 4);
            float xv[8] = {x0.x, x0.y, x0.z, x0.w, x1.x, x1.y, x1.z, x1.w};
            #pragma unroll
            for (int ii = 0; ii < 8; ii++) {
                ull xx = pack2(xv[ii], xv[ii]);
                a[ii][0] = ffma2(xx, vv.x, a[ii][0]);
                a[ii][1] = ffma2(xx, vv.y, a[ii][1]);
            }
        }
        __syncthreads();                       // all warps done reading panel p
        if (p + 1 < PPC) {
            #pragma unroll
            for (int r = 0; r < 5; r++) ((float4*)xs)[tid + r * 256] = px[r];
            ((float4*)vsp)[tid] = pv0;
            if (tid < 64)  ((float4*)vsp)[tid + 256] = pv1;
        }
    }

    // epilogue: red at w*RBLK + i*20 + rskew(i) + f  (per-warp padded blocks)
    #pragma unroll
    for (int ii = 0; ii < 8; ii++) {
        const int i = ig * 8 + ii;
        float* pr = sm + (size_t)w * RBLK + i * 20 + rskew(i) + fq * 4;
        *(ull*)(pr)     = a[ii][0];
        *(ull*)(pr + 2) = a[ii][1];
    }
    __syncthreads();

    // final: thread -> (i, f-quad): sum 8 warps, write partial z
    {
        const int i = tid >> 2, qd = tid & 3;
        float4 acc = make_float4(0.f, 0.f, 0.f, 0.f);
        #pragma unroll
        for (int ww = 0; ww < 8; ww++) {
            float4 v = *(const float4*)(sm + (size_t)ww * RBLK + i * 20 + rskew(i) + qd * 4);
            acc.x += v.x; acc.y += v.y; acc.z += v.z; acc.w += v.w;
        }
        *(float4*)(g_zpart + ((size_t)c * BATCH + b) * (FEAT * EIG)
                   + i * EIG + qd * 4) = acc;
    }
}

// ============================================================================
// Stage 1b: reduce partial z over 25 chunks (fixed order -> deterministic)
// ============================================================================
__global__ __launch_bounds__(256)
void k1_reduce() {
    const int q = blockIdx.x * 256 + threadIdx.x;   // over 8192 float4
    const float4* zp = (const float4*)g_zpart;
    float4 s = make_float4(0.f, 0.f, 0.f, 0.f);
    #pragma unroll
    for (int c = 0; c < NCHUNK; c++) {
        float4 v = zp[(size_t)c * (BATCH * FEAT * EIG / 4) + q];
        s.x += v.x; s.y += v.y; s.z += v.z; s.w += v.w;
    }
    ((float4*)g_z)[q] = s;
}

// ============================================================================
// Stage 2: w[b,j,e] = sum_{i,f} G[j,i,e,f] * z[b,i,f]
// ============================================================================
__global__ __launch_bounds__(128)
void k2_mix(const float* __restrict__ G) {
    const int bg = blockIdx.x;     // 0..3
    const int j  = blockIdx.y;     // 0..63
    const int tid = threadIdx.x;   // 128
    const int bl = tid >> 4;       // 0..7
    const int e  = tid & 15;
    const float* Gje  = G + (size_t)j * (FEAT * EIG * EIG) + e * EIG;
    const float* zrow = g_z + ((size_t)bg * 8 + bl) * (FEAT * EIG);
    ull acc0 = 0ULL, acc1 = 0ULL, acc2 = 0ULL, acc3 = 0ULL;
    #pragma unroll 8
    for (int i = 0; i < FEAT; i++) {
        const ulonglong2* gp = (const ulonglong2*)(Gje + (size_t)i * (EIG * EIG));
        const ulonglong2* zq = (const ulonglong2*)(zrow + i * EIG);
        ulonglong2 g0 = gp[0], g1 = gp[1], g2 = gp[2], g3 = gp[3];
        ulonglong2 z0 = zq[0], z1 = zq[1], z2 = zq[2], z3 = zq[3];
        acc0 = ffma2(g0.x, z0.x, acc0);
        acc1 = ffma2(g0.y, z0.y, acc1);
        acc2 = ffma2(g1.x, z1.x, acc2);
        acc3 = ffma2(g1.y, z1.y, acc3);
        acc0 = ffma2(g2.x, z2.x, acc0);
        acc1 = ffma2(g2.y, z2.y, acc1);
        acc2 = ffma2(g3.x, z3.x, acc2);
        acc3 = ffma2(g3.y, z3.y, acc3);
    }
    float2 f0 = unpack2(acc0), f1 = unpack2(acc1);
    float2 f2 = unpack2(acc2), f3 = unpack2(acc3);
    g_w[((size_t)bg * 8 + bl) * (NOUT * EIG) + j * EIG + e] =
        ((f0.x + f0.y) + (f1.x + f1.y)) + ((f2.x + f2.y) + (f3.x + f3.y));
}

// ============================================================================
// Stage 3: out[b,n,j] = sum_e V[n,e] * w[b,j,e]
// Block = (128-node tile, batch-PAIR), 256 thr: jp = tid&31 (j-pair),
// nb = tid>>5 (16-node slice). Thread holds w for 2 j x 2 BATCHES in regs
// (32 ull via padded wsT transpose) -> the per-node V broadcast (4 uniform
// LDS.128 = 16 crossbar cyc/warp) is amortized over 2 batches = 8 cyc per
// node-batch, matching the 8 fma cyc. V staged in smem (29-cyc lat, no DRAM
// latency exposure).
// ============================================================================
__global__ __launch_bounds__(256)
void k3_expand(const float* __restrict__ V, float* __restrict__ out) {
    __shared__ __align__(16) float vs[TN3 * EIG];        // 8 KB
    __shared__ __align__(16) float wsT[2][EIG * 65];     // 8.3 KB padded transpose
    const int b0 = blockIdx.y * 2;
    const int n0 = blockIdx.x * TN3;
    const int Nloc = (NODES - n0 < TN3) ? (NODES - n0) : TN3;   // 128 or 32
    const int tid = threadIdx.x;
    const int jp = tid & 31, nb = tid >> 5;

    // load w[b0], w[b0+1] transposed: wsT[bb][e*65 + j] = w[b][j][e]
    #pragma unroll
    for (int bb = 0; bb < 2; bb++) {
        float4 fw = ((const float4*)(g_w + (size_t)(b0 + bb) * NOUT * EIG))[tid];
        int j = tid >> 2, e0 = (tid & 3) * 4;
        wsT[bb][(e0 + 0) * 65 + j] = fw.x;
        wsT[bb][(e0 + 1) * 65 + j] = fw.y;
        wsT[bb][(e0 + 2) * 65 + j] = fw.z;
        wsT[bb][(e0 + 3) * 65 + j] = fw.w;
    }
    // cooperative load: V tile [Nloc][16]
    {
        const float4* src = (const float4*)(V + (size_t)n0 * EIG);
        for (int idx = tid; idx < Nloc * 4; idx += 256) ((float4*)vs)[idx] = src[idx];
    }
    __syncthreads();

    // w registers: e-pair packs for j = 2jp, 2jp+1, batches b0, b0+1 (32 ull)
    ull wA0[8], wA1[8], wB0[8], wB1[8];
    #pragma unroll
    for (int k = 0; k < 8; k++) {
        wA0[k] = pack2(wsT[0][(2*k)*65 + 2*jp],     wsT[0][(2*k+1)*65 + 2*jp]);
        wA1[k] = pack2(wsT[0][(2*k)*65 + 2*jp + 1], wsT[0][(2*k+1)*65 + 2*jp + 1]);
        wB0[k] = pack2(wsT[1][(2*k)*65 + 2*jp],     wsT[1][(2*k+1)*65 + 2*jp]);
        wB1[k] = pack2(wsT[1][(2*k)*65 + 2*jp + 1], wsT[1][(2*k+1)*65 + 2*jp + 1]);
    }

    float* obA = out + (size_t)(b0)     * NODES * NOUT + (size_t)n0 * NOUT + 2 * jp;
    float* obB = out + (size_t)(b0 + 1) * NODES * NOUT + (size_t)n0 * NOUT + 2 * jp;

    #pragma unroll 4
    for (int t = 0; t < 16; t++) {
        const int n = nb * 16 + t;               // warp-uniform
        if (n >= Nloc) break;
        const ulonglong2* vp = (const ulonglong2*)(vs + n * EIG);
        ulonglong2 va = vp[0], vb = vp[1];       // e 0..7 as 4 ull pairs
        ull aA0 = 0, aA1 = 0, aB0 = 0, aB1 = 0;
        aA0 = ffma2(va.x, wA0[0], aA0);  aA1 = ffma2(va.x, wA1[0], aA1);
        aB0 = ffma2(va.x, wB0[0], aB0);  aB1 = ffma2(va.x, wB1[0], aB1);
        aA0 = ffma2(va.y, wA0[1], aA0);  aA1 = ffma2(va.y, wA1[1], aA1);
        aB0 = ffma2(va.y, wB0[1], aB0);  aB1 = ffma2(va.y, wB1[1], aB1);
        aA0 = ffma2(vb.x, wA0[2], aA0);  aA1 = ffma2(vb.x, wA1[2], aA1);
        aB0 = ffma2(vb.x, wB0[2], aB0);  aB1 = ffma2(vb.x, wB1[2], aB1);
        aA0 = ffma2(vb.y, wA0[3], aA0);  aA1 = ffma2(vb.y, wA1[3], aA1);
        aB0 = ffma2(vb.y, wB0[3], aB0);  aB1 = ffma2(vb.y, wB1[3], aB1);
        ulonglong2 vc = vp[2], vd = vp[3];       // e 8..15
        aA0 = ffma2(vc.x, wA0[4], aA0);  aA1 = ffma2(vc.x, wA1[4], aA1);
        aB0 = ffma2(vc.x, wB0[4], aB0);  aB1 = ffma2(vc.x, wB1[4], aB1);
        aA0 = ffma2(vc.y, wA0[5], aA0);  aA1 = ffma2(vc.y, wA1[5], aA1);
        aB0 = ffma2(vc.y, wB0[5], aB0);  aB1 = ffma2(vc.y, wB1[5], aB1);
        aA0 = ffma2(vd.x, wA0[6], aA0);  aA1 = ffma2(vd.x, wA1[6], aA1);
        aB0 = ffma2(vd.x, wB0[6], aB0);  aB1 = ffma2(vd.x, wB1[6], aB1);
        aA0 = ffma2(vd.y, wA0[7], aA0);  aA1 = ffma2(vd.y, wA1[7], aA1);
        aB0 = ffma2(vd.y, wB0[7], aB0);  aB1 = ffma2(vd.y, wB1[7], aB1);
        float2 rA0 = unpack2(aA0), rA1 = unpack2(aA1);
        float2 rB0 = unpack2(aB0), rB1 = unpack2(aB1);
        *(float2*)(obA + (size_t)n * NOUT) = make_float2(rA0.x + rA0.y, rA1.x + rA1.y);
        *(float2*)(obB + (size_t)n * NOUT) = make_float2(rB0.x + rB0.y, rB1.x + rB1.y);
    }
}

extern "C" void kernel_launch(void* const* d_in, const int* in_sizes, int n_in,
                              void* d_out, int out_size) {
    const float* x = (const float*)d_in[0];   // (32, 20000, 64) fp32
    const float* V = (const float*)d_in[1];   // (20000, 16)     fp32
    const float* G = (const float*)d_in[2];   // (64, 64, 16, 16) fp32
    float* out = (float*)d_out;               // (32, 20000, 64) fp32

    k1_project<<<dim3(NCHUNK, BATCH), 256>>>(x, V);
    k1_reduce<<<32, 256>>>();
    k2_mix<<<dim3(4, NOUT), 128>>>(G);
    k3_expand<<<dim3(NBLK3, BATCH / 2), 256>>>(V, out);
}

// round 12
// speedup vs baseline: 1.3386x; 1.1138x over previous
#include <cuda_runtime.h>
#include <cstdint>

#define NODES 20000
#define BATCH 32
#define FEAT  64
#define EIG   16
#define NOUT  64

// k1: 25 chunks x 800 nodes x 16 batch-pairs; 20 cp.async panels of 40 nodes
#define NCHUNK 25
#define CH1    800
#define PN     40
#define NPAN   20
#define PFL    5760          // floats per panel buffer: xA 2560 | xB 2560 | V 640
#define XB_OFF 2560
#define V_OFF  5120

// k3: 157 tiles x 128 nodes (last tile 32), 16 batch-pairs
#define TN3    128
#define NBLK3  157

typedef unsigned long long ull;

// Scratch (static device globals: allocation-free per harness rules)
// g_zpart[c][bp][r][bb][i][f]: 25*16*4*2048 floats = 13.1 MB
__device__ float g_zpart[(size_t)NCHUNK * 16 * 4 * 2048];
__device__ float g_z[BATCH * FEAT * EIG];                      // 128 KB
__device__ float g_w[BATCH * NOUT * EIG];                      // 128 KB

// ---- packed fp32x2 helpers ----
__device__ __forceinline__ ull pack2(float lo, float hi) {
    ull r; asm("mov.b64 %0, {%1, %2};" : "=l"(r) : "f"(lo), "f"(hi)); return r;
}
__device__ __forceinline__ float2 unpack2(ull v) {
    float2 r; asm("mov.b64 {%0, %1}, %2;" : "=f"(r.x), "=f"(r.y) : "l"(v)); return r;
}
__device__ __forceinline__ ull ffma2(ull a, ull b, ull c) {
    ull d; asm("fma.rn.f32x2 %0, %1, %2, %3;" : "=l"(d) : "l"(a), "l"(b), "l"(c)); return d;
}
__device__ __forceinline__ ull fadd2(ull a, ull b) {
    ull d; asm("add.rn.f32x2 %0, %1, %2;" : "=l"(d) : "l"(a), "l"(b)); return d;
}

// ---- cp.async helpers ----
__device__ __forceinline__ void cpa16(uint32_t dst, const void* src) {
    asm volatile("cp.async.cg.shared.global [%0], [%1], 16;" :: "r"(dst), "l"(src));
}
__device__ __forceinline__ void cpa_commit() {
    asm volatile("cp.async.commit_group;");
}
__device__ __forceinline__ void cpa_wait0() {
    asm volatile("cp.async.wait_group 0;");
}

// ============================================================================
// Stage 1: z[b,i,f] = sum_m V[m,f] * x[b,m,i]   -- MIRRORS the measured-good
// k3 structure: block = (800-node tile, batch-PAIR), 256 thr, thread owns
// 2i x 2b x 16f (32 ull accum). Per node: V via 4 UNIFORM LDS.128 (16 crossbar
// cyc amortized over 2 batches) + x via 2 lane-distinct LDS.64 + 32 FFMA2 --
// exactly k3's measured 9.5ns/256-node-batch inner mix.
// x/V staged through cp.async DOUBLE-BUFFERED 40-node panels (23KB x 2):
// stage(p+1) issued after the barrier, overlapping compute(p).
// Epilogue: pairwise warp-reduce (8->4) via padded smem; g_zpart keeps an
// r(=warp-group) axis reduced later by k1_reduce.
// ============================================================================
__global__ __launch_bounds__(256)
void k1_project(const float* __restrict__ x, const float* __restrict__ V) {
    __shared__ __align__(16) float sm[2 * PFL];   // 46.08 KB
    const int c  = blockIdx.x;          // chunk 0..24
    const int bp = blockIdx.y;          // batch pair 0..15
    const int b0 = bp * 2;
    const int m0 = c * CH1;
    const int tid = threadIdx.x;
    const int w = tid >> 5, lane = tid & 31;
    const uint32_t smb = (uint32_t)__cvta_generic_to_shared(sm);

    const float* xA0 = x + ((size_t)b0 * NODES) * FEAT;
    const float* xB0 = xA0 + (size_t)NODES * FEAT;

    // ---- stage panel p into buffer (p&1) ----
    auto stage = [&](int p) {
        const int mp = m0 + p * PN;
        const uint32_t bufb = smb + (uint32_t)((p & 1) * PFL * 4);
        const float* sA = xA0 + (size_t)mp * FEAT;
        const float* sB = xB0 + (size_t)mp * FEAT;
        #pragma unroll
        for (int r = 0; r < 3; r++) {
            int i = tid + r * 256;
            if (i < 640) cpa16(bufb + i * 16, sA + i * 4);
        }
        #pragma unroll
        for (int r = 0; r < 3; r++) {
            int i = tid + r * 256;
            if (i < 640) cpa16(bufb + XB_OFF * 4 + i * 16, sB + i * 4);
        }
        if (tid < 160) cpa16(bufb + V_OFF * 4 + tid * 16, V + (size_t)mp * EIG + tid * 4);
        cpa_commit();
    };

    ull zA0[8], zA1[8], zB0[8], zB1[8];
    #pragma unroll
    for (int k = 0; k < 8; k++) { zA0[k]=0; zA1[k]=0; zB0[k]=0; zB1[k]=0; }

    stage(0);
    for (int p = 0; p < NPAN; p++) {
        cpa_wait0();
        __syncthreads();                 // panel p visible; buf (p+1)&1 free
        if (p + 1 < NPAN) stage(p + 1);  // overlaps with compute(p)
        const float* buf = sm + (p & 1) * PFL;
        #pragma unroll
        for (int t = 0; t < 5; t++) {
            const int n = t * 8 + w;     // this warp's node within the panel
            float2 xa = *(const float2*)(buf + n * FEAT + 2 * lane);
            float2 xb = *(const float2*)(buf + XB_OFF + n * FEAT + 2 * lane);
            const ulonglong2* vp = (const ulonglong2*)(buf + V_OFF + n * EIG);
            ulonglong2 v01 = vp[0], v23 = vp[1], v45 = vp[2], v67 = vp[3];
            ull q[8] = {v01.x, v01.y, v23.x, v23.y, v45.x, v45.y, v67.x, v67.y};
            ull xa0 = pack2(xa.x, xa.x), xa1 = pack2(xa.y, xa.y);
            ull xb0 = pack2(xb.x, xb.x), xb1 = pack2(xb.y, xb.y);
            #pragma unroll
            for (int k = 0; k < 8; k++) {
                zA0[k] = ffma2(xa0, q[k], zA0[k]);
                zA1[k] = ffma2(xa1, q[k], zA1[k]);
                zB0[k] = ffma2(xb0, q[k], zB0[k]);
                zB1[k] = ffma2(xb1, q[k], zB1[k]);
            }
        }
    }
    __syncthreads();   // done with panel buffers; reuse sm for reduction

    // ---- pairwise warp reduce: warps 4-7 stash, warps 0-3 add partner ----
    // lane row stride 66 floats (264B: 8B-aligned, 2-way bank spread)
    if (w >= 4) {
        float* pb = sm + (w - 4) * 2112 + lane * 66;
        #pragma unroll
        for (int k = 0; k < 8; k++) {
            *(ull*)(pb + 2 * k)      = zA0[k];
            *(ull*)(pb + 16 + 2 * k) = zA1[k];
            *(ull*)(pb + 32 + 2 * k) = zB0[k];
            *(ull*)(pb + 48 + 2 * k) = zB1[k];
        }
    }
    __syncthreads();
    if (w < 4) {
        const float* pb = sm + w * 2112 + lane * 66;
        #pragma unroll
        for (int k = 0; k < 8; k++) {
            zA0[k] = fadd2(zA0[k], *(const ull*)(pb + 2 * k));
            zA1[k] = fadd2(zA1[k], *(const ull*)(pb + 16 + 2 * k));
            zB0[k] = fadd2(zB0[k], *(const ull*)(pb + 32 + 2 * k));
            zB1[k] = fadd2(zB1[k], *(const ull*)(pb + 48 + 2 * k));
        }
        // write partial z: g_zpart[((c*16+bp)*4 + w)*2048 + bb*1024 + i*16 + f]
        float* gz = g_zpart + (((size_t)c * 16 + bp) * 4 + w) * 2048;
        #pragma unroll
        for (int bb = 0; bb < 2; bb++) {
            ull* zi0 = bb ? zB0 : zA0;
            ull* zi1 = bb ? zB1 : zA1;
            #pragma unroll
            for (int ii = 0; ii < 2; ii++) {
                ull* z = ii ? zi1 : zi0;
                float* row = gz + bb * 1024 + (2 * lane + ii) * EIG;
                #pragma unroll
                for (int q4 = 0; q4 < 4; q4++) {
                    float2 u0 = unpack2(z[2 * q4]);
                    float2 u1 = unpack2(z[2 * q4 + 1]);
                    *(float4*)(row + q4 * 4) = make_float4(u0.x, u0.y, u1.x, u1.y);
                }
            }
        }
    }
}

// ============================================================================
// Stage 1b: reduce partial z over 25 chunks x 4 warp-groups (fixed order)
// ============================================================================
__global__ __launch_bounds__(256)
void k1_reduce() {
    const int q = blockIdx.x * 256 + threadIdx.x;   // over 8192 float4
    const int b = q >> 8, rem = q & 255;
    const int bp = b >> 1, bb = b & 1;
    const float4* zp = (const float4*)g_zpart;
    float4 s = make_float4(0.f, 0.f, 0.f, 0.f);
    for (int c = 0; c < NCHUNK; c++) {
        #pragma unroll
        for (int r = 0; r < 4; r++) {
            float4 v = zp[(((size_t)c * 16 + bp) * 4 + r) * 512 + bb * 256 + rem];
            s.x += v.x; s.y += v.y; s.z += v.z; s.w += v.w;
        }
    }
    ((float4*)g_z)[q] = s;
}

// ============================================================================
// Stage 2: w[b,j,e] = sum_{i,f} G[j,i,e,f] * z[b,i,f]
// ============================================================================
__global__ __launch_bounds__(128)
void k2_mix(const float* __restrict__ G) {
    const int bg = blockIdx.x;     // 0..3
    const int j  = blockIdx.y;     // 0..63
    const int tid = threadIdx.x;   // 128
    const int bl = tid >> 4;       // 0..7
    const int e  = tid & 15;
    const float* Gje  = G + (size_t)j * (FEAT * EIG * EIG) + e * EIG;
    const float* zrow = g_z + ((size_t)bg * 8 + bl) * (FEAT * EIG);
    ull acc0 = 0ULL, acc1 = 0ULL, acc2 = 0ULL, acc3 = 0ULL;
    #pragma unroll 8
    for (int i = 0; i < FEAT; i++) {
        const ulonglong2* gp = (const ulonglong2*)(Gje + (size_t)i * (EIG * EIG));
        const ulonglong2* zq = (const ulonglong2*)(zrow + i * EIG);
        ulonglong2 g0 = gp[0], g1 = gp[1], g2 = gp[2], g3 = gp[3];
        ulonglong2 z0 = zq[0], z1 = zq[1], z2 = zq[2], z3 = zq[3];
        acc0 = ffma2(g0.x, z0.x, acc0);
        acc1 = ffma2(g0.y, z0.y, acc1);
        acc2 = ffma2(g1.x, z1.x, acc2);
        acc3 = ffma2(g1.y, z1.y, acc3);
        acc0 = ffma2(g2.x, z2.x, acc0);
        acc1 = ffma2(g2.y, z2.y, acc1);
        acc2 = ffma2(g3.x, z3.x, acc2);
        acc3 = ffma2(g3.y, z3.y, acc3);
    }
    float2 f0 = unpack2(acc0), f1 = unpack2(acc1);
    float2 f2 = unpack2(acc2), f3 = unpack2(acc3);
    g_w[((size_t)bg * 8 + bl) * (NOUT * EIG) + j * EIG + e] =
        ((f0.x + f0.y) + (f1.x + f1.y)) + ((f2.x + f2.y) + (f3.x + f3.y));
}

// ============================================================================
// Stage 3: out[b,n,j] = sum_e V[n,e] * w[b,j,e]   (R11 verbatim: 41.2us)
// ============================================================================
__global__ __launch_bounds__(256)
void k3_expand(const float* __restrict__ V, float* __restrict__ out) {
    __shared__ __align__(16) float vs[TN3 * EIG];        // 8 KB
    __shared__ __align__(16) float wsT[2][EIG * 65];     // 8.3 KB padded transpose
    const int b0 = blockIdx.y * 2;
    const int n0 = blockIdx.x * TN3;
    const int Nloc = (NODES - n0 < TN3) ? (NODES - n0) : TN3;   // 128 or 32
    const int tid = threadIdx.x;
    const int jp = tid & 31, nb = tid >> 5;

    #pragma unroll
    for (int bb = 0; bb < 2; bb++) {
        float4 fw = ((const float4*)(g_w + (size_t)(b0 + bb) * NOUT * EIG))[tid];
        int j = tid >> 2, e0 = (tid & 3) * 4;
        wsT[bb][(e0 + 0) * 65 + j] = fw.x;
        wsT[bb][(e0 + 1) * 65 + j] = fw.y;
        wsT[bb][(e0 + 2) * 65 + j] = fw.z;
        wsT[bb][(e0 + 3) * 65 + j] = fw.w;
    }
    {
        const float4* src = (const float4*)(V + (size_t)n0 * EIG);
        for (int idx = tid; idx < Nloc * 4; idx += 256) ((float4*)vs)[idx] = src[idx];
    }
    __syncthreads();

    ull wA0[8], wA1[8], wB0[8], wB1[8];
    #pragma unroll
    for (int k = 0; k < 8; k++) {
        wA0[k] = pack2(wsT[0][(2*k)*65 + 2*jp],     wsT[0][(2*k+1)*65 + 2*jp]);
        wA1[k] = pack2(wsT[0][(2*k)*65 + 2*jp + 1], wsT[0][(2*k+1)*65 + 2*jp + 1]);
        wB0[k] = pack2(wsT[1][(2*k)*65 + 2*jp],     wsT[1][(2*k+1)*65 + 2*jp]);
        wB1[k] = pack2(wsT[1][(2*k)*65 + 2*jp + 1], wsT[1][(2*k+1)*65 + 2*jp + 1]);
    }

    float* obA = out + (size_t)(b0)     * NODES * NOUT + (size_t)n0 * NOUT + 2 * jp;
    float* obB = out + (size_t)(b0 + 1) * NODES * NOUT + (size_t)n0 * NOUT + 2 * jp;

    #pragma unroll 4
    for (int t = 0; t < 16; t++) {
        const int n = nb * 16 + t;               // warp-uniform
        if (n >= Nloc) break;
        const ulonglong2* vp = (const ulonglong2*)(vs + n * EIG);
        ulonglong2 va = vp[0], vb = vp[1];
        ull aA0 = 0, aA1 = 0, aB0 = 0, aB1 = 0;
        aA0 = ffma2(va.x, wA0[0], aA0);  aA1 = ffma2(va.x, wA1[0], aA1);
        aB0 = ffma2(va.x, wB0[0], aB0);  aB1 = ffma2(va.x, wB1[0], aB1);
        aA0 = ffma2(va.y, wA0[1], aA0);  aA1 = ffma2(va.y, wA1[1], aA1);
        aB0 = ffma2(va.y, wB0[1], aB0);  aB1 = ffma2(va.y, wB1[1], aB1);
        aA0 = ffma2(vb.x, wA0[2], aA0);  aA1 = ffma2(vb.x, wA1[2], aA1);
        aB0 = ffma2(vb.x, wB0[2], aB0);  aB1 = ffma2(vb.x, wB1[2], aB1);
        aA0 = ffma2(vb.y, wA0[3], aA0);  aA1 = ffma2(vb.y, wA1[3], aA1);
        aB0 = ffma2(vb.y, wB0[3], aB0);  aB1 = ffma2(vb.y, wB1[3], aB1);
        ulonglong2 vc = vp[2], vd = vp[3];
        aA0 = ffma2(vc.x, wA0[4], aA0);  aA1 = ffma2(vc.x, wA1[4], aA1);
        aB0 = ffma2(vc.x, wB0[4], aB0);  aB1 = ffma2(vc.x, wB1[4], aB1);
        aA0 = ffma2(vc.y, wA0[5], aA0);  aA1 = ffma2(vc.y, wA1[5], aA1);
        aB0 = ffma2(vc.y, wB0[5], aB0);  aB1 = ffma2(vc.y, wB1[5], aB1);
        aA0 = ffma2(vd.x, wA0[6], aA0);  aA1 = ffma2(vd.x, wA1[6], aA1);
        aB0 = ffma2(vd.x, wB0[6], aB0);  aB1 = ffma2(vd.x, wB1[6], aB1);
        aA0 = ffma2(vd.y, wA0[7], aA0);  aA1 = ffma2(vd.y, wA1[7], aA1);
        aB0 = ffma2(vd.y, wB0[7], aB0);  aB1 = ffma2(vd.y, wB1[7], aB1);
        float2 rA0 = unpack2(aA0), rA1 = unpack2(aA1);
        float2 rB0 = unpack2(aB0), rB1 = unpack2(aB1);
        *(float2*)(obA + (size_t)n * NOUT) = make_float2(rA0.x + rA0.y, rA1.x + rA1.y);
        *(float2*)(obB + (size_t)n * NOUT) = make_float2(rB0.x + rB0.y, rB1.x + rB1.y);
    }
}

extern "C" void kernel_launch(void* const* d_in, const int* in_sizes, int n_in,
                              void* d_out, int out_size) {
    const float* x = (const float*)d_in[0];   // (32, 20000, 64) fp32
    const float* V = (const float*)d_in[1];   // (20000, 16)     fp32
    const float* G = (const float*)d_in[2];   // (64, 64, 16, 16) fp32
    float* out = (float*)d_out;               // (32, 20000, 64) fp32

    k1_project<<<dim3(NCHUNK, 16), 256>>>(x, V);
    k1_reduce<<<32, 256>>>();
    k2_mix<<<dim3(4, NOUT), 128>>>(G);
    k3_expand<<<dim3(NBLK3, BATCH / 2), 256>>>(V, out);
}